// round 6
// baseline (speedup 1.0000x reference)
#include <cuda_runtime.h>
#include <math.h>

// Problem constants (fixed shapes from the reference)
#define N_ENT   14541
#define N_REL   237
#define M_EDGES 272115
#define D       256
#define BS      16
#define NT      4          // entities per warp tile
#define OUT_ELEMS (N_ENT * BS)

typedef unsigned long long u64;

// Scratch (no cudaMalloc allowed)
__device__ float    g_sig[N_ENT * BS];
__device__ unsigned g_relmask[N_REL];

// acc += |e + nx| * r, all packed f32x2 (nx is pre-negated x).
// fma-pipe: FADD2 + FFMA2; alu-pipe: 2x LOP3 (sign clear).
__device__ __forceinline__ void l1term(u64& acc, u64 e, u64 nx, u64 r) {
    asm("{\n\t"
        ".reg .b64 t;\n\t"
        ".reg .b32 lo, hi;\n\t"
        "add.rn.f32x2 t, %1, %2;\n\t"
        "mov.b64 {lo, hi}, t;\n\t"
        "and.b32 lo, lo, 0x7FFFFFFF;\n\t"
        "and.b32 hi, hi, 0x7FFFFFFF;\n\t"
        "mov.b64 t, {lo, hi};\n\t"
        "fma.rn.f32x2 %0, t, %3, %0;\n\t"
        "}" : "+l"(acc) : "l"(e), "l"(nx), "l"(r));
}

__device__ __forceinline__ u64 packneg2(float a, float b) {
    u64 v;
    asm("mov.b64 %0, {%1, %2};" : "=l"(v) : "f"(-a), "f"(-b));
    return v;
}

__device__ __forceinline__ float unpack_sum(u64 v) {
    float lo, hi;
    asm("mov.b64 {%0, %1}, %2;" : "=f"(lo), "=f"(hi) : "l"(v));
    return lo + hi;
}

// ---------------------------------------------------------------------------
// dist: sig[n][b] = sigmoid(12 - sum_d |rel[b,d]| * |emb[b,d] - all_emb[n,d]|)
//       with sig[source_idx[b]][b] = 0 (sigmoid(12-1e8) == 0 in fp32)
// One warp handles NT=4 entities; lane owns d in {4L..4L+3} u {128+4L..128+4L+3},
// processed as packed f32x2 pairs. Side jobs: zero `out`, block 0 builds the
// relation->batch bitmask for the edge kernel (stream order => visibility).
// ---------------------------------------------------------------------------
__global__ void __launch_bounds__(256) dist_kernel(
    const float* __restrict__ emb,
    const float* __restrict__ all_emb,
    const float* __restrict__ tail_r,
    const int*   __restrict__ source_idx,
    const int*   __restrict__ relation_ids,
    float*       __restrict__ out)
{
    __shared__ __align__(16) float es[BS * D];   // emb[b][d]
    __shared__ __align__(16) float rs[BS * D];   // |tail_r[relation_ids[b]][d]|
    __shared__ int s_src[BS];

    const int tid  = threadIdx.x;
    const int lane = tid & 31;

    // Zero the output buffer (930 KB spread over 455 blocks, float2/thread).
    {
        const int i0 = (blockIdx.x * 256 + tid) * 2;
        if (i0 + 2 <= OUT_ELEMS)
            *(float2*)(out + i0) = make_float2(0.f, 0.f);
        else if (i0 < OUT_ELEMS)
            out[i0] = 0.f;
    }

    // Block 0: relation->batch bitmask for the edge kernel.
    if (blockIdx.x == 0 && tid < N_REL) {
        unsigned m = 0;
        #pragma unroll
        for (int b = 0; b < BS; b++)
            m |= (relation_ids[b] == tid) ? (1u << b) : 0u;
        g_relmask[tid] = m;
    }

    if (tid < BS) s_src[tid] = source_idx[tid];
    for (int i = tid; i < BS * D; i += 256) {
        int b = i >> 8;          // i / D
        int d = i & (D - 1);     // i % D
        es[i] = emb[i];
        rs[i] = fabsf(tail_r[relation_ids[b] * D + d]);
    }
    __syncthreads();

    const int warp = blockIdx.x * 8 + (tid >> 5);
    const int n0   = warp * NT;
    if (n0 >= N_ENT) return;

    // Preload all_emb rows for this tile (coalesced LDG.128), pre-negated
    // and packed as f32x2. x[n][0..3] covers d {4L,4L+1},{4L+2,4L+3},
    // {128+4L,128+4L+1},{128+4L+2,128+4L+3}.
    u64 x[NT][4];
    #pragma unroll
    for (int n = 0; n < NT; n++) {
        int nn = n0 + n; if (nn >= N_ENT) nn = N_ENT - 1;
        const float4* row = (const float4*)(all_emb + nn * D);
        float4 a = row[lane];
        float4 c = row[32 + lane];
        x[n][0] = packneg2(a.x, a.y);
        x[n][1] = packneg2(a.z, a.w);
        x[n][2] = packneg2(c.x, c.y);
        x[n][3] = packneg2(c.z, c.w);
    }

    u64 acc[NT * BS];
    #pragma unroll
    for (int i = 0; i < NT * BS; i++) acc[i] = 0ull;

    // es/rs viewed as packed pairs: 128 u64 per b-row.
    const u64* es8 = (const u64*)es;
    const u64* rs8 = (const u64*)rs;

    #pragma unroll
    for (int b = 0; b < BS; b++) {
        const int base = b * 128;
        u64 e0 = es8[base + 2 * lane];
        u64 e1 = es8[base + 2 * lane + 1];
        u64 e2 = es8[base + 64 + 2 * lane];
        u64 e3 = es8[base + 64 + 2 * lane + 1];
        u64 r0 = rs8[base + 2 * lane];
        u64 r1 = rs8[base + 2 * lane + 1];
        u64 r2 = rs8[base + 64 + 2 * lane];
        u64 r3 = rs8[base + 64 + 2 * lane + 1];
        #pragma unroll
        for (int n = 0; n < NT; n++) {
            u64& a = acc[n * BS + b];
            l1term(a, e0, x[n][0], r0);
            l1term(a, e1, x[n][1], r1);
            l1term(a, e2, x[n][2], r2);
            l1term(a, e3, x[n][3], r3);
        }
    }

    // Fold packed pairs to scalars, then value-splitting butterfly:
    // 64 partials -> 62 shuffles; lane L ends with flat sums 2L and 2L+1,
    // where flat = n_local*16 + b.
    float sac[NT * BS];
    #pragma unroll
    for (int i = 0; i < NT * BS; i++) sac[i] = unpack_sum(acc[i]);

    #pragma unroll
    for (int step = 0; step < 5; step++) {
        const int mask = 16 >> step;
        const int V    = 64 >> step;
        const bool hi  = (lane & mask) != 0;
        #pragma unroll
        for (int i = 0; i < V / 2; i++) {
            float send = hi ? sac[i]         : sac[i + V / 2];
            float keep = hi ? sac[i + V / 2] : sac[i];
            float other = __shfl_xor_sync(0xffffffffu, send, mask);
            sac[i] = keep + other;
        }
    }

    // Epilogue: mask + sigmoid, coalesced float2 store
    const int f  = 2 * lane;
    const int nn = n0 + (f >> 4);
    const int b  = f & 15;
    if (nn < N_ENT) {
        float s0 = 1.0f / (1.0f + __expf(sac[0] - 12.0f));
        float s1 = 1.0f / (1.0f + __expf(sac[1] - 12.0f));
        if (nn == s_src[b])     s0 = 0.0f;
        if (nn == s_src[b + 1]) s1 = 0.0f;
        *(float2*)(g_sig + nn * BS + b) = make_float2(s0, s1);
    }
}

// ---------------------------------------------------------------------------
// edge: one edge per thread. Coalesced rel load -> L1-resident bitmask probe;
// ~93% of threads exit immediately. Survivors gather sig[head][b] and
// atomically scatter-add onto out[b][tail].
// ---------------------------------------------------------------------------
__global__ void __launch_bounds__(256, 8) edge_kernel(
    const int* __restrict__ heads,
    const int* __restrict__ tails,
    const int* __restrict__ rels,
    float*     __restrict__ out)
{
    const int i = blockIdx.x * 256 + threadIdx.x;
    if (i >= M_EDGES) return;

    const int r = __ldg(rels + i);
    unsigned m = g_relmask[r];
    if (!m) return;

    const int h = __ldg(heads + i);
    const int t = __ldg(tails + i);
    do {
        int b = __ffs(m) - 1;
        m &= m - 1;
        atomicAdd(out + b * N_ENT + t, g_sig[h * BS + b]);
    } while (m);
}

// ---------------------------------------------------------------------------
extern "C" void kernel_launch(void* const* d_in, const int* in_sizes, int n_in,
                              void* d_out, int out_size) {
    const float* emb          = (const float*)d_in[0];
    const float* all_emb      = (const float*)d_in[1];
    const float* tail_r       = (const float*)d_in[2];
    const int*   source_idx   = (const int*)  d_in[3];
    const int*   relation_ids = (const int*)  d_in[4];
    const int*   heads        = (const int*)  d_in[5];
    const int*   tails        = (const int*)  d_in[6];
    const int*   edge_rels    = (const int*)  d_in[7];
    float*       out          = (float*)d_out;

    const int warps  = (N_ENT + NT - 1) / NT;      // 3636
    const int blocks = (warps + 7) / 8;            // 455
    dist_kernel<<<blocks, 256>>>(emb, all_emb, tail_r, source_idx,
                                 relation_ids, out);

    const int eblocks = (M_EDGES + 255) / 256;     // 1063
    edge_kernel<<<eblocks, 256>>>(heads, tails, edge_rels, out);
}

// round 7
// speedup vs baseline: 1.0036x; 1.0036x over previous
#include <cuda_runtime.h>
#include <math.h>

// Problem constants (fixed shapes from the reference)
#define N_ENT   14541
#define N_REL   237
#define M_EDGES 272115
#define D       256
#define BS      16
#define NT      4            // entities per warp tile
#define OUT_ELEMS (N_ENT * BS)

#define NBLK    455          // dist grid size (8 warps * NT entities each)
#define EPB     599          // edges per block: 455*599 = 272545 >= M_EDGES
#define REGION  9600         // per-block compact region (>= EPB*16 worst case)

// Scratch (static device arrays; no runtime allocation)
__device__ float        g_sig[N_ENT * BS];
__device__ unsigned     g_edgebuf[NBLK * REGION];   // packed (h<<18 | t<<4 | b)
__device__ int          g_bcount[NBLK];

// ---------------------------------------------------------------------------
// dist: sig[n][b] = sigmoid(12 - sum_d |rel[b,d]| * |emb[b,d] - all_emb[n,d]|)
//       with sig[source_idx[b]][b] = 0 (sigmoid(12-1e8) == 0 in fp32).
// One warp handles NT=4 entities; lane owns d in {4L..4L+3} u {128+4L..128+4L+3}.
// Post-compute, each block filters its 599-edge slice against the batch
// relations and appends surviving (h,t,b) triples to its private region —
// this overlaps with other blocks' compute waves. Also zeroes `out`.
// ---------------------------------------------------------------------------
__global__ void __launch_bounds__(256) dist_kernel(
    const float* __restrict__ emb,
    const float* __restrict__ all_emb,
    const float* __restrict__ tail_r,
    const int*   __restrict__ source_idx,
    const int*   __restrict__ relation_ids,
    const int*   __restrict__ heads,
    const int*   __restrict__ tails,
    const int*   __restrict__ rels,
    float*       __restrict__ out)
{
    __shared__ float    es[BS * D];     // emb[b][d]
    __shared__ float    rs[BS * D];     // |tail_r[relation_ids[b]][d]|
    __shared__ int      s_rel[BS];
    __shared__ int      s_src[BS];
    __shared__ unsigned s_mask[N_REL];  // relation -> batch bitmask
    __shared__ int      s_cnt;

    const int tid  = threadIdx.x;
    const int lane = tid & 31;

    // Phase A: zero output slice; stage batch indices.
    {
        const int i0 = (blockIdx.x * 256 + tid) * 2;
        if (i0 + 2 <= OUT_ELEMS)
            *(float2*)(out + i0) = make_float2(0.f, 0.f);
        else if (i0 < OUT_ELEMS)
            out[i0] = 0.f;
    }
    if (tid < BS) {
        s_rel[tid] = relation_ids[tid];
        s_src[tid] = source_idx[tid];
    }
    if (tid == 0) s_cnt = 0;
    __syncthreads();

    // Phase B: build relation->batch bitmask; stage emb and |rel| tiles.
    if (tid < N_REL) {
        unsigned m = 0;
        #pragma unroll
        for (int b = 0; b < BS; b++)
            m |= (s_rel[b] == tid) ? (1u << b) : 0u;
        s_mask[tid] = m;
    }
    for (int i = tid; i < BS * D; i += 256) {
        int b = i >> 8;          // i / D
        int d = i & (D - 1);     // i % D
        es[i] = emb[i];
        rs[i] = fabsf(tail_r[s_rel[b] * D + d]);
    }
    __syncthreads();

    // Phase C: distance compute (guarded, no early return — phase D follows).
    const int warp = blockIdx.x * 8 + (tid >> 5);
    const int n0   = warp * NT;
    if (n0 < N_ENT) {
        // Preload all_emb rows for this tile (coalesced LDG.128)
        float4 xl[NT], xh[NT];
        #pragma unroll
        for (int n = 0; n < NT; n++) {
            int nn = n0 + n; if (nn >= N_ENT) nn = N_ENT - 1;
            const float4* row = (const float4*)(all_emb + nn * D);
            xl[n] = row[lane];
            xh[n] = row[32 + lane];
        }

        float acc[NT * BS];
        #pragma unroll
        for (int i = 0; i < NT * BS; i++) acc[i] = 0.f;

        const float4* es4 = (const float4*)es;
        const float4* rs4 = (const float4*)rs;

        #pragma unroll
        for (int b = 0; b < BS; b++) {
            float4 e0 = es4[b * 64 + lane];
            float4 e1 = es4[b * 64 + 32 + lane];
            float4 r0 = rs4[b * 64 + lane];
            float4 r1 = rs4[b * 64 + 32 + lane];
            #pragma unroll
            for (int n = 0; n < NT; n++) {
                float s = acc[n * BS + b];
                s += r0.x * fabsf(e0.x - xl[n].x);
                s += r0.y * fabsf(e0.y - xl[n].y);
                s += r0.z * fabsf(e0.z - xl[n].z);
                s += r0.w * fabsf(e0.w - xl[n].w);
                s += r1.x * fabsf(e1.x - xh[n].x);
                s += r1.y * fabsf(e1.y - xh[n].y);
                s += r1.z * fabsf(e1.z - xh[n].z);
                s += r1.w * fabsf(e1.w - xh[n].w);
                acc[n * BS + b] = s;
            }
        }

        // Value-splitting butterfly: 64 partials -> 62 shuffles; lane L ends
        // with flat sums 2L and 2L+1, where flat = n_local*16 + b.
        #pragma unroll
        for (int step = 0; step < 5; step++) {
            const int mask = 16 >> step;
            const int V    = 64 >> step;
            const bool hi  = (lane & mask) != 0;
            #pragma unroll
            for (int i = 0; i < V / 2; i++) {
                float send = hi ? acc[i]         : acc[i + V / 2];
                float keep = hi ? acc[i + V / 2] : acc[i];
                float other = __shfl_xor_sync(0xffffffffu, send, mask);
                acc[i] = keep + other;
            }
        }

        // Epilogue: mask + sigmoid, coalesced float2 store
        const int f  = 2 * lane;
        const int nn = n0 + (f >> 4);
        const int b  = f & 15;
        if (nn < N_ENT) {
            float s0 = 1.0f / (1.0f + __expf(acc[0] - 12.0f));
            float s1 = 1.0f / (1.0f + __expf(acc[1] - 12.0f));
            if (nn == s_src[b])     s0 = 0.0f;
            if (nn == s_src[b + 1]) s1 = 0.0f;
            *(float2*)(g_sig + nn * BS + b) = make_float2(s0, s1);
        }
    }

    // Phase D: edge filtering for this block's slice (no dependency on sig;
    // warps start as soon as their own compute finishes).
    {
        const int lo = blockIdx.x * EPB;
        int hi = lo + EPB; if (hi > M_EDGES) hi = M_EDGES;
        unsigned* __restrict__ region = g_edgebuf + (size_t)blockIdx.x * REGION;
        for (int k = lo + tid; k < hi; k += 256) {
            const int r = __ldg(rels + k);
            unsigned m = s_mask[r];
            if (!m) continue;
            const unsigned h = (unsigned)__ldg(heads + k);
            const unsigned t = (unsigned)__ldg(tails + k);
            const unsigned base = (h << 18) | (t << 4);
            do {
                int b = __ffs(m) - 1;
                m &= m - 1;
                int pos = atomicAdd(&s_cnt, 1);
                region[pos] = base | (unsigned)b;
            } while (m);
        }
    }
    __syncthreads();
    if (tid == 0) g_bcount[blockIdx.x] = s_cnt;
}

// ---------------------------------------------------------------------------
// scatter: process only surviving triples (~18K total, ~40/block).
// ---------------------------------------------------------------------------
__global__ void __launch_bounds__(128) scatter_kernel(float* __restrict__ out)
{
    const int blk = blockIdx.x;
    const int cnt = g_bcount[blk];
    const unsigned* __restrict__ region = g_edgebuf + (size_t)blk * REGION;
    for (int i = threadIdx.x; i < cnt; i += 128) {
        const unsigned e = region[i];
        const unsigned b = e & 15u;
        const unsigned t = (e >> 4) & 16383u;
        const unsigned h = e >> 18;
        atomicAdd(out + b * N_ENT + t, g_sig[h * BS + b]);
    }
}

// ---------------------------------------------------------------------------
extern "C" void kernel_launch(void* const* d_in, const int* in_sizes, int n_in,
                              void* d_out, int out_size) {
    const float* emb          = (const float*)d_in[0];
    const float* all_emb      = (const float*)d_in[1];
    const float* tail_r       = (const float*)d_in[2];
    const int*   source_idx   = (const int*)  d_in[3];
    const int*   relation_ids = (const int*)  d_in[4];
    const int*   heads        = (const int*)  d_in[5];
    const int*   tails        = (const int*)  d_in[6];
    const int*   edge_rels    = (const int*)  d_in[7];
    float*       out          = (float*)d_out;

    dist_kernel<<<NBLK, 256>>>(emb, all_emb, tail_r, source_idx, relation_ids,
                               heads, tails, edge_rels, out);
    scatter_kernel<<<NBLK, 128>>>(out);
}